// round 7
// baseline (speedup 1.0000x reference)
#include <cuda_runtime.h>
#include <cuda_bf16.h>
#include <math.h>

#define NN 100000
#define EE 1600000
#define DD 64
#define CC 2

// Static device scratch (no allocation allowed)
__device__ int2     g_rc[EE];    // packed (row, col) per edge
__device__ int      g_deg[NN];   // in-degree WITH self loop (init 1)
__device__ float    g_dinv[NN];
__device__ float2   g_z0[NN];    // dinv * (x @ W.T)
__device__ float4   g_a1[NN];    // .xy = hop-1 accumulator, .z = dinv^2
__device__ float2   g_t2[NN];    // hop-2 accumulator
__device__ int      g_is64;
__device__ unsigned g_cnt = 0;   // barrier arrival count (self-resetting)
__device__ unsigned g_gen = 0;   // barrier generation (monotonic, replay-safe)

// no-return reductions (REDG)
__device__ __forceinline__ void red_add_f2(float2* p, float a, float b) {
    asm volatile("red.global.add.v2.f32 [%0], {%1, %2};"
                 :: "l"(p), "f"(a), "f"(b) : "memory");
}
__device__ __forceinline__ void red_add_1(int* p) {
    asm volatile("red.global.add.s32 [%0], %1;" :: "l"(p), "r"(1) : "memory");
}

// Software grid barrier. Safe because all blocks are co-resident
// (grid sized via cudaOccupancyMaxActiveBlocksPerMultiprocessor).
__device__ __forceinline__ void grid_barrier(int nblk) {
    __syncthreads();
    if (threadIdx.x == 0) {
        __threadfence();
        unsigned gen = *(volatile unsigned*)&g_gen;
        unsigned old = atomicAdd(&g_cnt, 1u);
        if (old == (unsigned)nblk - 1u) {
            *(volatile unsigned*)&g_cnt = 0u;
            __threadfence();
            atomicAdd(&g_gen, 1u);
        } else {
            while (*(volatile unsigned*)&g_gen == gen) { __nanosleep(64); }
        }
        __threadfence();
    }
    __syncthreads();
}

__global__ void __launch_bounds__(256, 6)
k_fused(const float* __restrict__ x, const void* __restrict__ edge,
        const float* __restrict__ W, const float* __restrict__ b,
        float* __restrict__ out, int n, int e, int nblk)
{
    __shared__ float sW[2 * DD];
    const int t   = threadIdx.x;
    const int tid = blockIdx.x * 256 + t;
    const int nth = nblk * 256;
    if (t < 2 * DD) sW[t] = W[t];

    // ---- P0: deg = 1; thread 0 detects edge dtype width ----
    if (tid == 0) {
        const long long* e64 = (const long long*)edge;
        int ok = 1;
        #pragma unroll 1
        for (int k = 0; k < 64; k++) {
            long long v = e64[k];
            if (v < 0 || v >= (long long)n) { ok = 0; break; }
        }
        g_is64 = ok;
    }
    for (int i = tid; i < n; i += nth) g_deg[i] = 1;
    grid_barrier(nblk);

    // ---- P1: convert edges -> int2, count in-degree (4 edges/thread) ----
    {
        const int is64 = g_is64;
        const int chunks = (e + 3) >> 2;
        for (int ch = tid; ch < chunks; ch += nth) {
            int base = ch * 4;
            int m = min(4, e - base);
            int r[4], c[4];
            if (is64) {
                const long long* e64 = (const long long*)edge;
                if (m == 4) {
                    longlong2 r01 = *(const longlong2*)(e64 + base);
                    longlong2 r23 = *(const longlong2*)(e64 + base + 2);
                    longlong2 c01 = *(const longlong2*)(e64 + e + base);
                    longlong2 c23 = *(const longlong2*)(e64 + e + base + 2);
                    r[0]=(int)r01.x; r[1]=(int)r01.y; r[2]=(int)r23.x; r[3]=(int)r23.y;
                    c[0]=(int)c01.x; c[1]=(int)c01.y; c[2]=(int)c23.x; c[3]=(int)c23.y;
                } else {
                    for (int k = 0; k < m; k++) { r[k]=(int)e64[base+k]; c[k]=(int)e64[e+base+k]; }
                }
            } else {
                const int* e32 = (const int*)edge;
                if (m == 4) {
                    int4 rr = *(const int4*)(e32 + base);
                    int4 cc = *(const int4*)(e32 + e + base);
                    r[0]=rr.x; r[1]=rr.y; r[2]=rr.z; r[3]=rr.w;
                    c[0]=cc.x; c[1]=cc.y; c[2]=cc.z; c[3]=cc.w;
                } else {
                    for (int k = 0; k < m; k++) { r[k]=e32[base+k]; c[k]=e32[e+base+k]; }
                }
            }
            #pragma unroll
            for (int k = 0; k < 4; k++) {
                if (k >= m) break;
                int rr = r[k], cc = c[k];
                if ((unsigned)rr >= (unsigned)n || (unsigned)cc >= (unsigned)n) { rr = 0; cc = 0; }
                g_rc[base + k] = make_int2(rr, cc);
                red_add_1(&g_deg[cc]);
            }
        }
    }
    grid_barrier(nblk);

    // ---- P2: warp-per-node projection; writes dinv, z0, a1(full), t2=0 ----
    {
        const int lane = t & 31;
        const int warps_total = nth >> 5;
        for (int gw = tid >> 5; gw < n; gw += warps_total) {
            const float* xr = x + (size_t)gw * DD;
            float a  = xr[lane];
            float b2 = xr[lane + 32];
            float s0 = a * sW[lane]      + b2 * sW[lane + 32];
            float s1 = a * sW[DD + lane] + b2 * sW[DD + lane + 32];
            #pragma unroll
            for (int o = 16; o; o >>= 1) {
                s0 += __shfl_xor_sync(0xffffffffu, s0, o);
                s1 += __shfl_xor_sync(0xffffffffu, s1, o);
            }
            if (lane == 0) {
                float d = rsqrtf((float)g_deg[gw]);
                g_dinv[gw] = d;
                g_z0[gw] = make_float2(d * s0, d * s1);
                g_a1[gw] = make_float4(0.f, 0.f, d * d, 0.f);
                g_t2[gw] = make_float2(0.f, 0.f);
            }
        }
    }
    grid_barrier(nblk);

    // ---- P3: hop 1: a1.xy[c] += z0[r]; self-loops as tail [e, e+n) ----
    for (int i = tid; i < e + n; i += nth) {
        if (i < e) {
            int2 rc = g_rc[i];
            float2 v = __ldg(&g_z0[rc.x]);
            red_add_f2((float2*)&g_a1[rc.y], v.x, v.y);
        } else {
            int j = i - e;
            float2 v = __ldg(&g_z0[j]);
            red_add_f2((float2*)&g_a1[j], v.x, v.y);
        }
    }
    grid_barrier(nblk);

    // ---- P4: hop 2: t2[c] += dinv2[r]*t1[r] (one 16B gather/edge) ----
    for (int i = tid; i < e + n; i += nth) {
        if (i < e) {
            int2 rc = g_rc[i];
            float4 a = __ldg(&g_a1[rc.x]);
            red_add_f2(&g_t2[rc.y], a.z * a.x, a.z * a.y);
        } else {
            int j = i - e;
            float4 a = __ldg(&g_a1[j]);
            red_add_f2(&g_t2[j], a.z * a.x, a.z * a.y);
        }
    }
    grid_barrier(nblk);

    // ---- P5: out = log_softmax(dinv * t2 + b) ----
    {
        const float b0 = b[0], b1 = b[1];
        for (int i = tid; i < n; i += nth) {
            float d = g_dinv[i];
            float2 y = g_t2[i];
            float l0 = d * y.x + b0;
            float l1 = d * y.y + b1;
            float m = fmaxf(l0, l1);
            float lse = m + logf(expf(l0 - m) + expf(l1 - m));
            *(float2*)(out + 2 * i) = make_float2(l0 - lse, l1 - lse);
        }
    }
}

// ---------------- launch ----------------

extern "C" void kernel_launch(void* const* d_in, const int* in_sizes, int n_in,
                              void* d_out, int out_size) {
    const float* x    = (const float*)d_in[0];
    const void*  edge = d_in[1];
    const float* W    = (const float*)d_in[2];
    const float* b    = (const float*)d_in[3];
    float*       out  = (float*)d_out;

    int n = in_sizes[0] / DD;   // 100000
    int e = in_sizes[1] / 2;    // 1600000

    int dev = 0, sms = 0, perSM = 0;
    cudaGetDevice(&dev);
    cudaDeviceGetAttribute(&sms, cudaDevAttrMultiProcessorCount, dev);
    cudaOccupancyMaxActiveBlocksPerMultiprocessor(&perSM, k_fused, 256, 0);
    if (perSM < 1) perSM = 1;
    int nblk = sms * perSM;

    k_fused<<<nblk, 256>>>(x, edge, W, b, out, n, e, nblk);
}

// round 8
// speedup vs baseline: 1.0992x; 1.0992x over previous
#include <cuda_runtime.h>
#include <cuda_bf16.h>
#include <math.h>

#define NN 100000
#define EE 1600000
#define DD 64
#define CC 2

// Static device scratch (no allocation allowed).
// g_deg starts zero-initialized (module load) and is reset to 0 by k_out
// at the end of every call -> every invocation sees deg == 0.
__device__ int2   g_rc[EE];    // packed (row, col) per edge
__device__ int    g_deg[NN];   // in-degree WITHOUT self loop
__device__ float  g_dinv[NN];
__device__ float2 g_z0[NN];    // dinv * (x @ W.T)
__device__ float4 g_a1[NN];    // .xy = hop-1 accumulator t1, .z = dinv^2
__device__ float2 g_t2[NN];    // hop-2 accumulator

// no-return reductions (REDG)
__device__ __forceinline__ void red_add_f2(float2* p, float a, float b) {
    asm volatile("red.global.add.v2.f32 [%0], {%1, %2};"
                 :: "l"(p), "f"(a), "f"(b) : "memory");
}
__device__ __forceinline__ void red_add_1(int* p) {
    asm volatile("red.global.add.s32 [%0], %1;" :: "l"(p), "r"(1) : "memory");
}

// ---------------- kernels ----------------

// convert edge_index -> packed int2, count in-degree. 4 edges per thread.
// Edge dtype width detected per block (warp 0, L2-hot after first block).
__global__ void k_count(const void* __restrict__ edge, int e, int n) {
    __shared__ int s_is64;
    {
        int lane = threadIdx.x;
        if (lane < 32) {
            const long long* e64 = (const long long*)edge;
            long long v0 = e64[lane];
            long long v1 = e64[lane + 32];
            int ok = (v0 >= 0) && (v0 < (long long)n) &&
                     (v1 >= 0) && (v1 < (long long)n);
            unsigned ball = __ballot_sync(0xffffffffu, ok);
            if (lane == 0) s_is64 = (ball == 0xffffffffu);
        }
    }
    __syncthreads();
    const int is64 = s_is64;

    int base = (blockIdx.x * blockDim.x + threadIdx.x) * 4;
    if (base >= e) return;
    int r[4], c[4];
    int m = min(4, e - base);
    if (is64) {
        const long long* e64 = (const long long*)edge;
        if (m == 4) {
            longlong2 r01 = *(const longlong2*)(e64 + base);
            longlong2 r23 = *(const longlong2*)(e64 + base + 2);
            longlong2 c01 = *(const longlong2*)(e64 + e + base);
            longlong2 c23 = *(const longlong2*)(e64 + e + base + 2);
            r[0]=(int)r01.x; r[1]=(int)r01.y; r[2]=(int)r23.x; r[3]=(int)r23.y;
            c[0]=(int)c01.x; c[1]=(int)c01.y; c[2]=(int)c23.x; c[3]=(int)c23.y;
        } else {
            for (int k = 0; k < m; k++) { r[k]=(int)e64[base+k]; c[k]=(int)e64[e+base+k]; }
        }
    } else {
        const int* e32 = (const int*)edge;
        if (m == 4) {
            int4 rr = *(const int4*)(e32 + base);
            int4 cc = *(const int4*)(e32 + e + base);
            r[0]=rr.x; r[1]=rr.y; r[2]=rr.z; r[3]=rr.w;
            c[0]=cc.x; c[1]=cc.y; c[2]=cc.z; c[3]=cc.w;
        } else {
            for (int k = 0; k < m; k++) { r[k]=e32[base+k]; c[k]=e32[e+base+k]; }
        }
    }
    #pragma unroll
    for (int k = 0; k < 4; k++) {
        if (k >= m) break;
        int rr = r[k], cc = c[k];
        if ((unsigned)rr >= (unsigned)n || (unsigned)cc >= (unsigned)n) { rr = 0; cc = 0; }
        g_rc[base + k] = make_int2(rr, cc);
        red_add_1(&g_deg[cc]);
    }
}

// warp-per-node: dinv = rsqrt(deg+1); z0 = dinv*(x@W.T); a1=(0,0,d^2,0); t2=0
__global__ void k_proj(const float* __restrict__ x, const float* __restrict__ W, int n) {
    __shared__ float sW[2 * DD];
    int t = threadIdx.x;
    if (t < 2 * DD) sW[t] = W[t];
    __syncthreads();
    int gw = (blockIdx.x * blockDim.x + t) >> 5;
    int lane = t & 31;
    if (gw >= n) return;
    const float* xr = x + (size_t)gw * DD;
    float a  = xr[lane];
    float b2 = xr[lane + 32];
    float s0 = a * sW[lane]      + b2 * sW[lane + 32];
    float s1 = a * sW[DD + lane] + b2 * sW[DD + lane + 32];
    #pragma unroll
    for (int o = 16; o; o >>= 1) {
        s0 += __shfl_xor_sync(0xffffffffu, s0, o);
        s1 += __shfl_xor_sync(0xffffffffu, s1, o);
    }
    if (lane == 0) {
        float d = rsqrtf((float)(g_deg[gw] + 1));
        g_dinv[gw] = d;
        g_z0[gw] = make_float2(d * s0, d * s1);
        g_a1[gw] = make_float4(0.f, 0.f, d * d, 0.f);
        g_t2[gw] = make_float2(0.f, 0.f);
    }
}

// hop 1: a1.xy[c] += z0[r]; edges [0,e) + self-loop tail [e, e+n)
__global__ void k_edge1(int e, int n) {
    int i = blockIdx.x * blockDim.x + threadIdx.x;
    if (i < e) {
        int2 rc = g_rc[i];
        float2 v = __ldg(&g_z0[rc.x]);
        red_add_f2((float2*)&g_a1[rc.y], v.x, v.y);
    } else if (i < e + n) {
        int j = i - e;
        float2 v = __ldg(&g_z0[j]);
        red_add_f2((float2*)&g_a1[j], v.x, v.y);
    }
}

// hop 2: t2[c] += dinv2[r]*t1[r], one 16B gather per edge
__global__ void k_edge2(int e, int n) {
    int i = blockIdx.x * blockDim.x + threadIdx.x;
    if (i < e) {
        int2 rc = g_rc[i];
        float4 a = __ldg(&g_a1[rc.x]);
        red_add_f2(&g_t2[rc.y], a.z * a.x, a.z * a.y);
    } else if (i < e + n) {
        int j = i - e;
        float4 a = __ldg(&g_a1[j]);
        red_add_f2(&g_t2[j], a.z * a.x, a.z * a.y);
    }
}

// out = log_softmax(dinv * t2 + b); also resets deg to 0 for the next call
__global__ void k_out(const float* __restrict__ b, float* __restrict__ out, int n) {
    int i = blockIdx.x * blockDim.x + threadIdx.x;
    if (i >= n) return;
    float d = g_dinv[i];
    float2 y = g_t2[i];
    float l0 = d * y.x + b[0];
    float l1 = d * y.y + b[1];
    float m = fmaxf(l0, l1);
    float lse = m + logf(expf(l0 - m) + expf(l1 - m));
    *(float2*)(out + 2 * i) = make_float2(l0 - lse, l1 - lse);
    g_deg[i] = 0;
}

// ---------------- launch ----------------

extern "C" void kernel_launch(void* const* d_in, const int* in_sizes, int n_in,
                              void* d_out, int out_size) {
    const float* x    = (const float*)d_in[0];
    const void*  edge = d_in[1];
    const float* W    = (const float*)d_in[2];
    const float* b    = (const float*)d_in[3];
    float*       out  = (float*)d_out;

    int n = in_sizes[0] / DD;   // 100000
    int e = in_sizes[1] / 2;    // 1600000

    const int T = 256;
    int gn  = (n + T - 1) / T;
    int gc  = ((e + 3) / 4 + T - 1) / T;
    int gen = (e + n + T - 1) / T;
    int gw  = ((size_t)n * 32 + T - 1) / T;

    k_count<<<gc, T>>>(edge, e, n);
    k_proj<<<gw, T>>>(x, W, n);
    k_edge1<<<gen, T>>>(e, n);
    k_edge2<<<gen, T>>>(e, n);
    k_out<<<gn, T>>>(b, out, n);
}

// round 9
// speedup vs baseline: 1.1778x; 1.0715x over previous
#include <cuda_runtime.h>
#include <cuda_bf16.h>
#include <math.h>

#define NN 100000
#define EE 1600000
#define DD 64
#define CC 2

// Static device scratch (no allocation allowed).
// g_deg is zero at module load and reset to 0 by k_scale every call.
__device__ int2   g_rc[EE];    // packed (row, col) per edge
__device__ int    g_deg[NN];   // in-degree WITHOUT self loop
__device__ float  g_dinv[NN];
__device__ float2 g_y0[NN];    // x @ W.T (unscaled)
__device__ float2 g_z0[NN];    // dinv * y0
__device__ float4 g_a1[NN];    // .xy = hop-1 accumulator t1, .z = dinv^2
__device__ float2 g_t2[NN];    // hop-2 accumulator

// no-return reductions (REDG)
__device__ __forceinline__ void red_add_f2(float2* p, float a, float b) {
    asm volatile("red.global.add.v2.f32 [%0], {%1, %2};"
                 :: "l"(p), "f"(a), "f"(b) : "memory");
}
__device__ __forceinline__ void red_add_1(int* p) {
    asm volatile("red.global.add.s32 [%0], %1;" :: "l"(p), "r"(1) : "memory");
}

// ---------------- kernels ----------------

// Fused front end: blocks [0, gc) convert edges + count degree;
// blocks [gc, gc+gw) compute y0 = x @ W.T (warp-per-node).
// The two halves are data-independent; no synchronization needed.
__global__ void k_count_mv(const void* __restrict__ edge,
                           const float* __restrict__ x,
                           const float* __restrict__ W,
                           int e, int n, int gc) {
    if ((int)blockIdx.x < gc) {
        // ---- edge conversion + degree count (4 edges/thread) ----
        __shared__ int s_is64;
        if (threadIdx.x < 32) {
            const long long* e64 = (const long long*)edge;
            long long v0 = e64[threadIdx.x];
            long long v1 = e64[threadIdx.x + 32];
            int ok = (v0 >= 0) && (v0 < (long long)n) &&
                     (v1 >= 0) && (v1 < (long long)n);
            unsigned ball = __ballot_sync(0xffffffffu, ok);
            if (threadIdx.x == 0) s_is64 = (ball == 0xffffffffu);
        }
        __syncthreads();
        const int is64 = s_is64;

        int base = (blockIdx.x * blockDim.x + threadIdx.x) * 4;
        if (base >= e) return;
        int r[4], c[4];
        int m = min(4, e - base);
        if (is64) {
            const long long* e64 = (const long long*)edge;
            if (m == 4) {
                longlong2 r01 = *(const longlong2*)(e64 + base);
                longlong2 r23 = *(const longlong2*)(e64 + base + 2);
                longlong2 c01 = *(const longlong2*)(e64 + e + base);
                longlong2 c23 = *(const longlong2*)(e64 + e + base + 2);
                r[0]=(int)r01.x; r[1]=(int)r01.y; r[2]=(int)r23.x; r[3]=(int)r23.y;
                c[0]=(int)c01.x; c[1]=(int)c01.y; c[2]=(int)c23.x; c[3]=(int)c23.y;
            } else {
                for (int k = 0; k < m; k++) { r[k]=(int)e64[base+k]; c[k]=(int)e64[e+base+k]; }
            }
        } else {
            const int* e32 = (const int*)edge;
            if (m == 4) {
                int4 rr = *(const int4*)(e32 + base);
                int4 cc = *(const int4*)(e32 + e + base);
                r[0]=rr.x; r[1]=rr.y; r[2]=rr.z; r[3]=rr.w;
                c[0]=cc.x; c[1]=cc.y; c[2]=cc.z; c[3]=cc.w;
            } else {
                for (int k = 0; k < m; k++) { r[k]=e32[base+k]; c[k]=e32[e+base+k]; }
            }
        }
        #pragma unroll
        for (int k = 0; k < 4; k++) {
            if (k >= m) break;
            int rr = r[k], cc = c[k];
            if ((unsigned)rr >= (unsigned)n || (unsigned)cc >= (unsigned)n) { rr = 0; cc = 0; }
            g_rc[base + k] = make_int2(rr, cc);
            red_add_1(&g_deg[cc]);
        }
    } else {
        // ---- matvec: y0 = x @ W.T, warp-per-node ----
        __shared__ float sW[2 * DD];
        int t = threadIdx.x;
        if (t < 2 * DD) sW[t] = W[t];
        __syncthreads();
        int gw = (((int)blockIdx.x - gc) * blockDim.x + t) >> 5;
        int lane = t & 31;
        if (gw >= n) return;
        const float* xr = x + (size_t)gw * DD;
        float a  = xr[lane];
        float b2 = xr[lane + 32];
        float s0 = a * sW[lane]      + b2 * sW[lane + 32];
        float s1 = a * sW[DD + lane] + b2 * sW[DD + lane + 32];
        #pragma unroll
        for (int o = 16; o; o >>= 1) {
            s0 += __shfl_xor_sync(0xffffffffu, s0, o);
            s1 += __shfl_xor_sync(0xffffffffu, s1, o);
        }
        if (lane == 0) g_y0[gw] = make_float2(s0, s1);
    }
}

// scale: dinv = rsqrt(deg+1); z0 = dinv*y0; a1 = (0,0,d^2,0); t2 = 0; deg = 0
__global__ void k_scale(int n) {
    int i = blockIdx.x * blockDim.x + threadIdx.x;
    if (i >= n) return;
    float d = rsqrtf((float)(g_deg[i] + 1));
    g_deg[i] = 0;
    g_dinv[i] = d;
    float2 y = g_y0[i];
    g_z0[i] = make_float2(d * y.x, d * y.y);
    g_a1[i] = make_float4(0.f, 0.f, d * d, 0.f);
    g_t2[i] = make_float2(0.f, 0.f);
}

// hop 1: a1.xy[c] += z0[r]; edges [0,e) + self-loop tail [e, e+n)
__global__ void k_edge1(int e, int n) {
    int i = blockIdx.x * blockDim.x + threadIdx.x;
    if (i < e) {
        int2 rc = g_rc[i];
        float2 v = __ldg(&g_z0[rc.x]);
        red_add_f2((float2*)&g_a1[rc.y], v.x, v.y);
    } else if (i < e + n) {
        int j = i - e;
        float2 v = __ldg(&g_z0[j]);
        red_add_f2((float2*)&g_a1[j], v.x, v.y);
    }
}

// hop 2: t2[c] += dinv2[r]*t1[r], one 16B gather per edge
__global__ void k_edge2(int e, int n) {
    int i = blockIdx.x * blockDim.x + threadIdx.x;
    if (i < e) {
        int2 rc = g_rc[i];
        float4 a = __ldg(&g_a1[rc.x]);
        red_add_f2(&g_t2[rc.y], a.z * a.x, a.z * a.y);
    } else if (i < e + n) {
        int j = i - e;
        float4 a = __ldg(&g_a1[j]);
        red_add_f2(&g_t2[j], a.z * a.x, a.z * a.y);
    }
}

// out = log_softmax(dinv * t2 + b)
__global__ void k_out(const float* __restrict__ b, float* __restrict__ out, int n) {
    int i = blockIdx.x * blockDim.x + threadIdx.x;
    if (i >= n) return;
    float d = g_dinv[i];
    float2 y = g_t2[i];
    float l0 = d * y.x + b[0];
    float l1 = d * y.y + b[1];
    float m = fmaxf(l0, l1);
    float lse = m + logf(expf(l0 - m) + expf(l1 - m));
    *(float2*)(out + 2 * i) = make_float2(l0 - lse, l1 - lse);
}

// ---------------- launch ----------------

extern "C" void kernel_launch(void* const* d_in, const int* in_sizes, int n_in,
                              void* d_out, int out_size) {
    const float* x    = (const float*)d_in[0];
    const void*  edge = d_in[1];
    const float* W    = (const float*)d_in[2];
    const float* b    = (const float*)d_in[3];
    float*       out  = (float*)d_out;

    int n = in_sizes[0] / DD;   // 100000
    int e = in_sizes[1] / 2;    // 1600000

    const int T = 256;
    int gn  = (n + T - 1) / T;
    int gc  = ((e + 3) / 4 + T - 1) / T;
    int gen = (e + n + T - 1) / T;
    int gw  = ((size_t)n * 32 + T - 1) / T;

    k_count_mv<<<gc + gw, T>>>(edge, x, W, e, n, gc);
    k_scale<<<gn, T>>>(n);
    k_edge1<<<gen, T>>>(e, n);
    k_edge2<<<gen, T>>>(e, n);
    k_out<<<gn, T>>>(b, out, n);
}